// round 10
// baseline (speedup 1.0000x reference)
#include <cuda_runtime.h>
#include <cuda_bf16.h>

// QuantumConv2d on GB300 — direct tensor-product RX application, persistent grid.
//
// Per 2x2 patch (x0,x1,x2,x3):
//   t_k = A[k&3] + B[k>>2]  (signed sums, sign + iff bit set, LSB-first)
//   phase_k = -(t/2 + t^2/4)          [global phase dropped]
//   d_k = exp(i phase_k)
//   y = (RX(w3)(x)RX(w2)(x)RX(w1)(x)RX(w0)) d as 4 commuting single-qubit
//       stages: pair (a, b=a^2^q): y_a = c a - i s b, y_b = -i s a + c b.
//       Packed (re,im): -i s b = (s*bi, -s*br) = (s,-s) .* swap(b)
//   0.25 initial-state amplitude folded into stage-3 coefficients.
//   state_{F(j)} = y_j, F = CNOT-ring perm {0,14,15,1,13,3,2,12,9,7,6,8,4,10,11,5}
//   out_q = sum_{j: bit(3-q) of F(j)} |y_j|^2
//
// R8/R9 lesson: f32x2-packing scalar sections (phase poly, epilogue) loses to
// issue stalls; only the RX stages (naturally complex pairs) stay packed.
// This round: persistent 740-block grid (148 SM x 5 blocks) removes the
// 5.53-wave quantization tail and amortizes the weight sincos setup.

#define PK2(d, lo, hi)   asm("mov.b64 %0, {%1, %2};" : "=l"(d) : "f"(lo), "f"(hi))
#define UPK2(lo, hi, d)  asm("mov.b64 {%0, %1}, %2;" : "=f"(lo), "=f"(hi) : "l"(d))
#define MUL2(d, a, b)    asm("mul.rn.f32x2 %0, %1, %2;" : "=l"(d) : "l"(a), "l"(b))
#define FMA2(d, a, b, c) asm("fma.rn.f32x2 %0, %1, %2, %3;" : "=l"(d) : "l"(a), "l"(b), "l"(c))

#define NPATCH (1 << 20)
#define GRID   740
#define TPB    256

__global__ __launch_bounds__(TPB) void qconv_kernel(const float* __restrict__ x,
                                                    const float* __restrict__ w,
                                                    float4* __restrict__ out) {
    // per-thread RX coefficients (amortized over the grid-stride loop)
    float c[4], s[4];
    #pragma unroll
    for (int q = 0; q < 4; q++)
        __sincosf(0.5f * w[q], &s[q], &c[q]);
    c[3] *= 0.25f;   // fold |psi0| amplitude into last stage
    s[3] *= 0.25f;

    for (int tid = blockIdx.x * TPB + threadIdx.x; tid < NPATCH; tid += GRID * TPB) {
        int b  = tid >> 14;
        int jj = (tid >> 7) & 127;
        int ii = tid & 127;

        const float* p = x + (b << 16) + (jj << 9) + (ii << 1);
        float2 a01 = *(const float2*)(p);
        float2 a23 = *(const float2*)(p + 256);
        float x0 = a01.x, x1 = a01.y, x2 = a23.x, x3 = a23.y;

        float A[4] = {-x0 - x1,  x0 - x1, -x0 + x1,  x0 + x1};
        float B[4] = {-x2 - x3,  x2 - x3, -x2 + x3,  x2 + x3};

        // phases + cis (scalar — measured faster than packed variants)
        unsigned long long v[16];   // packed (re, im)
        #pragma unroll
        for (int k = 0; k < 16; k++) {
            float t  = A[k & 3] + B[k >> 2];
            float ph = t * fmaf(-0.25f, t, -0.5f);   // -(t/2 + t^2/4)
            float sn, cs;
            __sincosf(ph, &sn, &cs);
            PK2(v[k], cs, sn);
        }

        // 4 single-qubit RX stages (commuting), packed complex
        #pragma unroll
        for (int q = 0; q < 4; q++) {
            int m = 1 << q;
            float cq = c[q], sq = s[q], nsq = -s[q];
            unsigned long long C2, S2;
            PK2(C2, cq, cq);      // (c,  c)
            PK2(S2, sq, nsq);     // (s, -s)
            #pragma unroll
            for (int k = 0; k < 16; k++) {
                if (!(k & m)) {
                    unsigned long long a = v[k], bb = v[k | m];
                    float ar, ai, br, bi;
                    UPK2(ar, ai, a);
                    UPK2(br, bi, bb);
                    unsigned long long sa, sb;        // swapped halves
                    PK2(sa, ai, ar);
                    PK2(sb, bi, br);
                    unsigned long long ta, tb, ya, yb;
                    MUL2(ta, a, C2);
                    MUL2(tb, bb, C2);
                    FMA2(ya, sb, S2, ta);             // c*a + (s*bi, -s*br)
                    FMA2(yb, sa, S2, tb);             // c*b + (s*ai, -s*ar)
                    v[k] = ya; v[k | m] = yb;
                }
            }
        }

        // probabilities (scalar, wide ILP)
        float pr[16];
        #pragma unroll
        for (int j = 0; j < 16; j++) {
            float re, im;
            UPK2(re, im, v[j]);
            pr[j] = fmaf(re, re, im * im);
        }

        // grouped accumulation through F = {0,14,15,1,13,3,2,12,9,7,6,8,4,10,11,5}
        float T1 = pr[9]  + pr[10] + pr[12] + pr[15];
        float T2 = pr[8]  + pr[11] + pr[13] + pr[14];
        float T3 = pr[1]  + pr[2]  + pr[4]  + pr[7];
        float U1 = pr[3]  + pr[4]  + pr[8]  + pr[15];
        float U2 = pr[1]  + pr[6]  + pr[10] + pr[13];
        float U3 = pr[2]  + pr[5]  + pr[9]  + pr[14];
        float o0 = T2 + T3;   // bit 3 of F(j)
        float o1 = T1 + T3;   // bit 2
        float o2 = U2 + U3;   // bit 1
        float o3 = U1 + U3;   // bit 0

        out[tid] = make_float4(o0, o1, o2, o3);
    }
}

extern "C" void kernel_launch(void* const* d_in, const int* in_sizes, int n_in,
                              void* d_out, int out_size) {
    const float* x = (const float*)d_in[0];
    const float* w = (const float*)d_in[1];
    if (n_in >= 2 && in_sizes[0] == 4) {   // robustness if metadata order differs
        x = (const float*)d_in[1];
        w = (const float*)d_in[0];
    }
    qconv_kernel<<<GRID, TPB>>>(x, w, (float4*)d_out);
}

// round 11
// speedup vs baseline: 1.1502x; 1.1502x over previous
#include <cuda_runtime.h>
#include <cuda_bf16.h>

// QuantumConv2d on GB300 — direct tensor-product RX application (no WHT, no smem).
//
// Per 2x2 patch (x0,x1,x2,x3):
//   t_k = A[k&3] + B[k>>2]  (signed sums, sign + iff bit set, LSB-first)
//   phase_k = -(t/2 + t^2/4)          [global phase dropped]
//   d_k = exp(i phase_k)
//   y = (RX(w3)(x)RX(w2)(x)RX(w1)(x)RX(w0)) d as 4 commuting single-qubit
//       stages: pair (a, b=a^2^q): y_a = c a - i s b, y_b = -i s a + c b.
//       Packed (re,im): -i s b = (s*bi, -s*br) = (s,-s) .* swap(b)
//   0.25 initial-state amplitude folded into stage-3 coefficients.
//   state_{F(j)} = y_j, F = CNOT-ring perm {0,14,15,1,13,3,2,12,9,7,6,8,4,10,11,5}
//   out_q = sum_{j: bit(3-q) of F(j)} |y_j|^2
//
// Config history: R7 body (scalar phase/epilogue, packed RX) is the measured
// optimum; R8/R9 packing variants and R10 persistent grid all regressed.
// This round: 128-thread blocks, grid 8192 — 11 blocks/SM at 44 regs gives
// 68.75% occupancy ceiling and 5.03 waves (vs 5.54), keeping scheduler slack.

#define PK2(d, lo, hi)   asm("mov.b64 %0, {%1, %2};" : "=l"(d) : "f"(lo), "f"(hi))
#define UPK2(lo, hi, d)  asm("mov.b64 {%0, %1}, %2;" : "=f"(lo), "=f"(hi) : "l"(d))
#define MUL2(d, a, b)    asm("mul.rn.f32x2 %0, %1, %2;" : "=l"(d) : "l"(a), "l"(b))
#define FMA2(d, a, b, c) asm("fma.rn.f32x2 %0, %1, %2, %3;" : "=l"(d) : "l"(a), "l"(b), "l"(c))

#define TPB 128

__global__ __launch_bounds__(TPB) void qconv_kernel(const float* __restrict__ x,
                                                    const float* __restrict__ w,
                                                    float4* __restrict__ out) {
    // per-thread RX coefficients (w is uniform -> L1/L2 cached)
    float c[4], s[4];
    #pragma unroll
    for (int q = 0; q < 4; q++)
        __sincosf(0.5f * w[q], &s[q], &c[q]);
    c[3] *= 0.25f;   // fold |psi0| amplitude into last stage
    s[3] *= 0.25f;

    int tid = blockIdx.x * TPB + threadIdx.x;   // = b*16384 + jj*128 + ii
    int b  = tid >> 14;
    int jj = (tid >> 7) & 127;
    int ii = tid & 127;

    const float* p = x + (b << 16) + (jj << 9) + (ii << 1);
    float2 a01 = *(const float2*)(p);
    float2 a23 = *(const float2*)(p + 256);
    float x0 = a01.x, x1 = a01.y, x2 = a23.x, x3 = a23.y;

    float A[4] = {-x0 - x1,  x0 - x1, -x0 + x1,  x0 + x1};
    float B[4] = {-x2 - x3,  x2 - x3, -x2 + x3,  x2 + x3};

    // phases + cis (scalar — measured faster than packed variants)
    unsigned long long v[16];   // packed (re, im)
    #pragma unroll
    for (int k = 0; k < 16; k++) {
        float t  = A[k & 3] + B[k >> 2];
        float ph = t * fmaf(-0.25f, t, -0.5f);   // -(t/2 + t^2/4)
        float sn, cs;
        __sincosf(ph, &sn, &cs);
        PK2(v[k], cs, sn);
    }

    // 4 single-qubit RX stages (commuting), packed complex
    #pragma unroll
    for (int q = 0; q < 4; q++) {
        int m = 1 << q;
        float cq = c[q], sq = s[q], nsq = -s[q];
        unsigned long long C2, S2;
        PK2(C2, cq, cq);      // (c,  c)
        PK2(S2, sq, nsq);     // (s, -s)
        #pragma unroll
        for (int k = 0; k < 16; k++) {
            if (!(k & m)) {
                unsigned long long a = v[k], bb = v[k | m];
                float ar, ai, br, bi;
                UPK2(ar, ai, a);
                UPK2(br, bi, bb);
                unsigned long long sa, sb;        // swapped halves
                PK2(sa, ai, ar);
                PK2(sb, bi, br);
                unsigned long long ta, tb, ya, yb;
                MUL2(ta, a, C2);
                MUL2(tb, bb, C2);
                FMA2(ya, sb, S2, ta);             // c*a + (s*bi, -s*br)
                FMA2(yb, sa, S2, tb);             // c*b + (s*ai, -s*ar)
                v[k] = ya; v[k | m] = yb;
            }
        }
    }

    // probabilities (scalar, wide ILP)
    float pr[16];
    #pragma unroll
    for (int j = 0; j < 16; j++) {
        float re, im;
        UPK2(re, im, v[j]);
        pr[j] = fmaf(re, re, im * im);
    }

    // grouped accumulation through F = {0,14,15,1,13,3,2,12,9,7,6,8,4,10,11,5}
    float T1 = pr[9]  + pr[10] + pr[12] + pr[15];
    float T2 = pr[8]  + pr[11] + pr[13] + pr[14];
    float T3 = pr[1]  + pr[2]  + pr[4]  + pr[7];
    float U1 = pr[3]  + pr[4]  + pr[8]  + pr[15];
    float U2 = pr[1]  + pr[6]  + pr[10] + pr[13];
    float U3 = pr[2]  + pr[5]  + pr[9]  + pr[14];
    float o0 = T2 + T3;   // bit 3 of F(j)
    float o1 = T1 + T3;   // bit 2
    float o2 = U2 + U3;   // bit 1
    float o3 = U1 + U3;   // bit 0

    out[tid] = make_float4(o0, o1, o2, o3);
}

extern "C" void kernel_launch(void* const* d_in, const int* in_sizes, int n_in,
                              void* d_out, int out_size) {
    const float* x = (const float*)d_in[0];
    const float* w = (const float*)d_in[1];
    if (n_in >= 2 && in_sizes[0] == 4) {   // robustness if metadata order differs
        x = (const float*)d_in[1];
        w = (const float*)d_in[0];
    }
    qconv_kernel<<<8192, TPB>>>(x, w, (float4*)d_out);
}